// round 9
// baseline (speedup 1.0000x reference)
#include <cuda_runtime.h>
#include <cuda_bf16.h>
#include <cstdint>

#define NN 50000
#define EE 800000
#define CH 256
#define PAD_M 50048          // 391 * 128

// ---- scratch (device globals; no allocation allowed) ----
__device__ __align__(16) float g_xw[(size_t)NN * CH];              // x @ W (51.2 MB)
__device__ int   g_deg[NN];
__device__ int   g_off[NN + 1];
__device__ int   g_cur[NN];
__device__ __align__(16) int2 g_epack[EE];                         // (src, val)
__device__ __align__(16) __nv_bfloat16 g_xhi[(size_t)PAD_M * CH];  // 25.6 MB
__device__ __align__(16) __nv_bfloat16 g_xlo[(size_t)PAD_M * CH];  // 25.6 MB
__device__ __align__(16) __nv_bfloat16 g_wthi[CH * CH];            // W^T hi [n][k]
__device__ __align__(16) __nv_bfloat16 g_wtlo[CH * CH];            // W^T lo [n][k]

// =============================================================== helpers
__device__ __forceinline__ uint32_t smem_u32(const void* p) {
    uint32_t a;
    asm("{ .reg .u64 t; cvta.to.shared.u64 t, %1; cvt.u32.u64 %0, t; }"
        : "=r"(a) : "l"(p));
    return a;
}

__device__ __forceinline__ void cp_async16(uint32_t s, const void* g) {
    asm volatile("cp.async.cg.shared.global [%0], [%1], 16;" :: "r"(s), "l"(g));
}
__device__ __forceinline__ void cp_commit() {
    asm volatile("cp.async.commit_group;" ::: "memory");
}
template <int N>
__device__ __forceinline__ void cp_wait() {
    asm volatile("cp.async.wait_group %0;" :: "n"(N) : "memory");
}

__device__ __forceinline__ void ldsm_x4(uint32_t* r, uint32_t addr) {
    asm volatile("ldmatrix.sync.aligned.m8n8.x4.shared.b16 {%0,%1,%2,%3}, [%4];"
                 : "=r"(r[0]), "=r"(r[1]), "=r"(r[2]), "=r"(r[3]) : "r"(addr));
}

// D(fp32) += A(bf16) * B(bf16), m16n8k16, A row-major frag, B col-major frag
__device__ __forceinline__ void mma_bf16(float* c, const uint32_t* a, const uint32_t* b) {
    asm volatile(
        "mma.sync.aligned.m16n8k16.row.col.f32.bf16.bf16.f32 "
        "{%0,%1,%2,%3}, {%4,%5,%6,%7}, {%8,%9}, {%0,%1,%2,%3};"
        : "+f"(c[0]), "+f"(c[1]), "+f"(c[2]), "+f"(c[3])
        : "r"(a[0]), "r"(a[1]), "r"(a[2]), "r"(a[3]), "r"(b[0]), "r"(b[1]));
}

// =============================================================== CSR build
__global__ void hist_kernel(const int* __restrict__ dst, int E) {
    int i = blockIdx.x * blockDim.x + threadIdx.x;
    if (i < E) atomicAdd(&g_deg[dst[i]], 1);
}

// single-pass SMEM scan: 1024 threads x 49 elements each (50176 >= NN)
#define SCAN_PER_T 49
#define SCAN_PAD   (1024 * SCAN_PER_T)           // 50176
#define SCAN_SMEM  (SCAN_PAD * 4)                // 200704 B

__global__ __launch_bounds__(1024) void scan_smem_kernel(int E) {
    extern __shared__ int sd[];
    __shared__ int wsum[32];
    int tid = threadIdx.x, lane = tid & 31, warp = tid >> 5;

    for (int i = tid; i < SCAN_PAD; i += 1024)
        sd[i] = (i < NN) ? g_deg[i] : 0;
    __syncthreads();

    int base = tid * SCAN_PER_T;
    int local = 0;
    for (int j = 0; j < SCAN_PER_T; j++) local += sd[base + j];

    int x = local;
    #pragma unroll
    for (int o = 1; o < 32; o <<= 1) {
        int y = __shfl_up_sync(0xffffffffu, x, o);
        if (lane >= o) x += y;
    }
    if (lane == 31) wsum[warp] = x;
    __syncthreads();
    if (warp == 0) {
        int t = wsum[lane];
        #pragma unroll
        for (int o = 1; o < 32; o <<= 1) {
            int y = __shfl_up_sync(0xffffffffu, t, o);
            if (lane >= o) t += y;
        }
        wsum[lane] = t;
    }
    __syncthreads();
    int run = x - local + (warp > 0 ? wsum[warp - 1] : 0);

    for (int j = 0; j < SCAN_PER_T; j++) {
        int v = sd[base + j];
        sd[base + j] = run;
        run += v;
    }
    __syncthreads();
    for (int i = tid; i < NN; i += 1024) {
        int v = sd[i];
        g_off[i] = v;
        g_cur[i] = v;
    }
    if (tid == 0) g_off[NN] = E;
}

__global__ void scatter_kernel(const int* __restrict__ src,
                               const int* __restrict__ dst,
                               const float* __restrict__ val, int E) {
    int i = blockIdx.x * blockDim.x + threadIdx.x;
    if (i < E) {
        int p = atomicAdd(&g_cur[dst[i]], 1);
        g_epack[p] = make_int2(src[i], __float_as_int(val[i]));
    }
}

// =============================================================== split prep
__global__ void split_x_kernel(const float* __restrict__ x, int n4) {
    int i = blockIdx.x * blockDim.x + threadIdx.x;
    if (i >= n4) return;
    float4 v = ((const float4*)x)[i];
    union { __nv_bfloat16 b[4]; uint2 u; } H, L;
    H.b[0] = __float2bfloat16(v.x); L.b[0] = __float2bfloat16(v.x - __bfloat162float(H.b[0]));
    H.b[1] = __float2bfloat16(v.y); L.b[1] = __float2bfloat16(v.y - __bfloat162float(H.b[1]));
    H.b[2] = __float2bfloat16(v.z); L.b[2] = __float2bfloat16(v.z - __bfloat162float(H.b[2]));
    H.b[3] = __float2bfloat16(v.w); L.b[3] = __float2bfloat16(v.w - __bfloat162float(H.b[3]));
    ((uint2*)g_xhi)[i] = H.u;
    ((uint2*)g_xlo)[i] = L.u;
}

__global__ void zero_pad_kernel(int M) {
    int i = blockIdx.x * blockDim.x + threadIdx.x;
    size_t base = (size_t)M * CH;
    size_t total = (size_t)PAD_M * CH;
    size_t idx = base + i;
    if (idx < total) {
        g_xhi[idx] = __float2bfloat16(0.f);
        g_xlo[idx] = __float2bfloat16(0.f);
    }
}

__global__ void split_wt_kernel(const float* __restrict__ W) {
    int k = threadIdx.x;
    int n = blockIdx.x;
    float w = W[k * CH + n];
    __nv_bfloat16 h = __float2bfloat16(w);
    g_wthi[n * CH + k] = h;
    g_wtlo[n * CH + k] = __float2bfloat16(w - __bfloat162float(h));
}

// =============================================================== mma.sync GEMM
// g_xw[M, bn..bn+127] = x @ W[:, bn..bn+127] via split-bf16
// (D += AhiBhi + AhiBlo + AloBhi, fp32 accum). One N-half per launch.
#define SWZ(r, c) ((uint32_t)((r) * 64 + (((c) ^ ((r) & 3)) * 16)))
#define GEMM_SMEM 65536

__global__ __launch_bounds__(256, 2) void gemm_mma(int M, int bn) {
    extern __shared__ char smem[];
    const uint32_t sb = smem_u32(smem);
    const int tid  = threadIdx.x;
    const int lane = tid & 31;
    const int wid  = tid >> 5;
    const int warp_m = (wid & 3) * 32;   // 0,32,64,96
    const int warp_n = (wid >> 2) * 64;  // 0,64
    const size_t arow = (size_t)blockIdx.x * 128;

    float acc[2][8][4];
    #pragma unroll
    for (int mt = 0; mt < 2; mt++)
        #pragma unroll
        for (int nt = 0; nt < 8; nt++)
            #pragma unroll
            for (int j = 0; j < 4; j++) acc[mt][nt][j] = 0.f;

    auto fill = [&](int buf, int ch) {
        const int k0 = ch * 32;
        const uint32_t base = sb + buf * 32768;
        #pragma unroll
        for (int i = 0; i < 2; i++) {
            int chunk = tid + i * 256;         // 0..511
            int r = chunk >> 2, c = chunk & 3; // row 0..127, 16B-chunk 0..3
            uint32_t so = SWZ(r, c);
            size_t ga = (arow + r) * CH + k0 + c * 8;
            size_t gb = (size_t)(bn + r) * CH + k0 + c * 8;
            cp_async16(base +     0 + so, &g_xhi[ga]);
            cp_async16(base +  8192 + so, &g_xlo[ga]);
            cp_async16(base + 16384 + so, &g_wthi[gb]);
            cp_async16(base + 24576 + so, &g_wtlo[gb]);
        }
    };

    auto compute = [&](int buf) {
        const uint32_t base = sb + buf * 32768;
        #pragma unroll
        for (int ks = 0; ks < 2; ks++) {
            uint32_t a_hi[2][4], a_lo[2][4];
            const int achunk = 2 * ks + (lane >> 4);
            #pragma unroll
            for (int mt = 0; mt < 2; mt++) {
                int r = warp_m + mt * 16 + (lane & 15);
                uint32_t ad = base + SWZ(r, achunk);
                ldsm_x4(a_hi[mt], ad);
                ldsm_x4(a_lo[mt], ad + 8192);
            }
            #pragma unroll
            for (int np = 0; np < 4; np++) {
                int nr = warp_n + np * 16 + (lane & 7) + ((lane & 16) ? 8 : 0);
                int bchunk = 2 * ks + ((lane >> 3) & 1);
                uint32_t bd = base + 16384 + SWZ(nr, bchunk);
                uint32_t bhi[4], blo[4];
                ldsm_x4(bhi, bd);
                ldsm_x4(blo, bd + 8192);
                #pragma unroll
                for (int h = 0; h < 2; h++) {
                    int nt = np * 2 + h;
                    #pragma unroll
                    for (int mt = 0; mt < 2; mt++) {
                        mma_bf16(acc[mt][nt], a_hi[mt], &bhi[2 * h]);
                        mma_bf16(acc[mt][nt], a_hi[mt], &blo[2 * h]);
                        mma_bf16(acc[mt][nt], a_lo[mt], &bhi[2 * h]);
                    }
                }
            }
        }
    };

    fill(0, 0);
    cp_commit();
    #pragma unroll 1
    for (int ch = 0; ch < 8; ch++) {
        if (ch < 7) {
            fill((ch + 1) & 1, ch + 1);
            cp_commit();
            cp_wait<1>();
        } else {
            cp_wait<0>();
        }
        __syncthreads();
        compute(ch & 1);
        __syncthreads();
    }

    #pragma unroll
    for (int mt = 0; mt < 2; mt++) {
        size_t r0 = arow + warp_m + mt * 16 + (lane >> 2);
        #pragma unroll
        for (int nt = 0; nt < 8; nt++) {
            int gc = bn + warp_n + nt * 8 + 2 * (lane & 3);
            if (r0 < (size_t)M)
                *(float2*)&g_xw[r0 * CH + gc] =
                    make_float2(acc[mt][nt][0], acc[mt][nt][1]);
            if (r0 + 8 < (size_t)M)
                *(float2*)&g_xw[(r0 + 8) * CH + gc] =
                    make_float2(acc[mt][nt][2], acc[mt][nt][3]);
        }
    }
}

// =============================================================== gather
// out[d][c0+c] = b[c0+c] + sum_{edges to d} val * xw[src][c0+c]
// One 128-channel half per launch; 8 nodes per 256-thread block.
__global__ __launch_bounds__(256) void gather_half(const float* __restrict__ bias,
                                                   float* __restrict__ out, int c0) {
    int node = blockIdx.x * 8 + (threadIdx.x >> 5);
    if (node >= NN) return;
    int c = c0 + ((threadIdx.x & 31) << 2);
    int s = g_off[node], e = g_off[node + 1];
    float4 acc = *(const float4*)&bias[c];
    int j = s;
    for (; j + 4 <= e; j += 4) {
        int2 e0 = g_epack[j],     e1 = g_epack[j + 1];
        int2 e2 = g_epack[j + 2], e3 = g_epack[j + 3];
        float v0 = __int_as_float(e0.y), v1 = __int_as_float(e1.y);
        float v2 = __int_as_float(e2.y), v3 = __int_as_float(e3.y);
        float4 x0 = *(const float4*)&g_xw[(size_t)e0.x * CH + c];
        float4 x1 = *(const float4*)&g_xw[(size_t)e1.x * CH + c];
        float4 x2 = *(const float4*)&g_xw[(size_t)e2.x * CH + c];
        float4 x3 = *(const float4*)&g_xw[(size_t)e3.x * CH + c];
        acc.x += v0 * x0.x; acc.y += v0 * x0.y; acc.z += v0 * x0.z; acc.w += v0 * x0.w;
        acc.x += v1 * x1.x; acc.y += v1 * x1.y; acc.z += v1 * x1.z; acc.w += v1 * x1.w;
        acc.x += v2 * x2.x; acc.y += v2 * x2.y; acc.z += v2 * x2.z; acc.w += v2 * x2.w;
        acc.x += v3 * x3.x; acc.y += v3 * x3.y; acc.z += v3 * x3.z; acc.w += v3 * x3.w;
    }
    for (; j < e; ++j) {
        int2 ep = g_epack[j];
        float v = __int_as_float(ep.y);
        float4 x0 = *(const float4*)&g_xw[(size_t)ep.x * CH + c];
        acc.x += v * x0.x; acc.y += v * x0.y; acc.z += v * x0.z; acc.w += v * x0.w;
    }
    *(float4*)&out[(size_t)node * CH + c] = acc;
}

// =============================================================== launch
// DAG (captured with forked streams so branches overlap at replay):
//   sD:   split_wt -> split_x -> pad                       -> evD
//   sB:   memset(deg) -> hist -> scan -> scatter           -> evS
//   main: [evD] gemm(n=0..127) -> evG0 -> gemm(n=128..255) -> evG1
//   sC:   [evG0 && evS] gather cols 0..127                 -> evC
//   sD:   [evG1 && evS] gather cols 128..255               -> evD2
//   main: join evC, evD2
extern "C" void kernel_launch(void* const* d_in, const int* in_sizes, int n_in,
                              void* d_out, int out_size) {
    const float* x    = (const float*)d_in[0];   // [N, 256]
    const float* W    = (const float*)d_in[1];   // [256, 256]
    const float* bias = (const float*)d_in[2];   // [256]
    const int*   esrc = (const int*)d_in[3];     // [E]
    const int*   edst = (const int*)d_in[4];     // [E]
    const float* eval = (const float*)d_in[5];   // [E]
    float* out = (float*)d_out;

    int M = in_sizes[0] / CH;   // 50000
    int E = in_sizes[3];        // 800000

    cudaFuncSetAttribute(gemm_mma, cudaFuncAttributeMaxDynamicSharedMemorySize,
                         GEMM_SMEM);
    cudaFuncSetAttribute(scan_smem_kernel,
                         cudaFuncAttributeMaxDynamicSharedMemorySize, SCAN_SMEM);

    cudaStream_t sB, sC, sD;
    cudaStreamCreateWithFlags(&sB, cudaStreamNonBlocking);
    cudaStreamCreateWithFlags(&sC, cudaStreamNonBlocking);
    cudaStreamCreateWithFlags(&sD, cudaStreamNonBlocking);
    cudaEvent_t evRoot, evS, evD, evG0, evG1, evC, evD2;
    cudaEventCreateWithFlags(&evRoot, cudaEventDisableTiming);
    cudaEventCreateWithFlags(&evS,    cudaEventDisableTiming);
    cudaEventCreateWithFlags(&evD,    cudaEventDisableTiming);
    cudaEventCreateWithFlags(&evG0,   cudaEventDisableTiming);
    cudaEventCreateWithFlags(&evG1,   cudaEventDisableTiming);
    cudaEventCreateWithFlags(&evC,    cudaEventDisableTiming);
    cudaEventCreateWithFlags(&evD2,   cudaEventDisableTiming);

    // fork sB, sD off the (captured) default stream
    cudaEventRecord(evRoot, 0);
    cudaStreamWaitEvent(sB, evRoot, 0);
    cudaStreamWaitEvent(sD, evRoot, 0);

    // ---- branch D: split prep (off the GEMM critical path) ----
    split_wt_kernel<<<CH, CH, 0, sD>>>(W);
    int n4 = (M * CH) / 4;
    split_x_kernel<<<(n4 + 255) / 256, 256, 0, sD>>>(x, n4);
    int padn = (PAD_M - M) * CH;
    if (padn > 0) zero_pad_kernel<<<(padn + 255) / 256, 256, 0, sD>>>(M);
    cudaEventRecord(evD, sD);

    // ---- branch B: CSR-by-dst build ----
    void* degp = nullptr;
    cudaGetSymbolAddress(&degp, g_deg);
    cudaMemsetAsync(degp, 0, NN * sizeof(int), sB);
    hist_kernel<<<(E + 255) / 256, 256, 0, sB>>>(edst, E);
    scan_smem_kernel<<<1, 1024, SCAN_SMEM, sB>>>(E);
    scatter_kernel<<<(E + 255) / 256, 256, 0, sB>>>(esrc, edst, eval, E);
    cudaEventRecord(evS, sB);

    // ---- main branch: GEMM halves ----
    cudaStreamWaitEvent(0, evD, 0);
    int mblk = (M + 127) / 128;   // 391
    gemm_mma<<<mblk, 256, GEMM_SMEM>>>(M, 0);
    cudaEventRecord(evG0, 0);
    gemm_mma<<<mblk, 256, GEMM_SMEM>>>(M, 128);
    cudaEventRecord(evG1, 0);

    // ---- concurrent gather halves on sC / sD ----
    cudaStreamWaitEvent(sC, evG0, 0);
    cudaStreamWaitEvent(sC, evS, 0);
    gather_half<<<(NN + 7) / 8, 256, 0, sC>>>(bias, out, 0);
    cudaEventRecord(evC, sC);

    cudaStreamWaitEvent(sD, evG1, 0);
    cudaStreamWaitEvent(sD, evS, 0);
    gather_half<<<(NN + 7) / 8, 256, 0, sD>>>(bias, out, 128);
    cudaEventRecord(evD2, sD);

    // ---- join ----
    cudaStreamWaitEvent(0, evC, 0);
    cudaStreamWaitEvent(0, evD2, 0);

    cudaEventDestroy(evRoot);
    cudaEventDestroy(evS);
    cudaEventDestroy(evD);
    cudaEventDestroy(evG0);
    cudaEventDestroy(evG1);
    cudaEventDestroy(evC);
    cudaEventDestroy(evD2);
    cudaStreamDestroy(sB);
    cudaStreamDestroy(sC);
    cudaStreamDestroy(sD);
}

// round 10
// speedup vs baseline: 1.0413x; 1.0413x over previous
#include <cuda_runtime.h>
#include <cuda_bf16.h>
#include <cuda_fp16.h>
#include <cstdint>

#define NN 50000
#define EE 800000
#define CH 256
#define PAD_M 50048          // 391 * 128

// ---- scratch (device globals; no allocation allowed) ----
__device__ __align__(16) __half g_xwh[(size_t)NN * CH];            // x @ W (25.6 MB, fp16)
__device__ int   g_deg[NN];
__device__ int   g_off[NN + 1];
__device__ int   g_cur[NN];
__device__ int   g_esrc[EE];
__device__ float g_eval[EE];
__device__ __align__(16) __nv_bfloat16 g_xhi[(size_t)PAD_M * CH];  // 25.6 MB
__device__ __align__(16) __nv_bfloat16 g_xlo[(size_t)PAD_M * CH];  // 25.6 MB
__device__ __align__(16) __nv_bfloat16 g_wthi[CH * CH];            // W^T hi [n][k]
__device__ __align__(16) __nv_bfloat16 g_wtlo[CH * CH];            // W^T lo [n][k]

// =============================================================== helpers
__device__ __forceinline__ uint32_t smem_u32(const void* p) {
    uint32_t a;
    asm("{ .reg .u64 t; cvta.to.shared.u64 t, %1; cvt.u32.u64 %0, t; }"
        : "=r"(a) : "l"(p));
    return a;
}

__device__ __forceinline__ void cp_async16(uint32_t s, const void* g) {
    asm volatile("cp.async.cg.shared.global [%0], [%1], 16;" :: "r"(s), "l"(g));
}
__device__ __forceinline__ void cp_commit() {
    asm volatile("cp.async.commit_group;" ::: "memory");
}
template <int N>
__device__ __forceinline__ void cp_wait() {
    asm volatile("cp.async.wait_group %0;" :: "n"(N) : "memory");
}

__device__ __forceinline__ void ldsm_x4(uint32_t* r, uint32_t addr) {
    asm volatile("ldmatrix.sync.aligned.m8n8.x4.shared.b16 {%0,%1,%2,%3}, [%4];"
                 : "=r"(r[0]), "=r"(r[1]), "=r"(r[2]), "=r"(r[3]) : "r"(addr));
}

// D(fp32) += A(bf16) * B(bf16), m16n8k16, A row-major frag, B col-major frag
__device__ __forceinline__ void mma_bf16(float* c, const uint32_t* a, const uint32_t* b) {
    asm volatile(
        "mma.sync.aligned.m16n8k16.row.col.f32.bf16.bf16.f32 "
        "{%0,%1,%2,%3}, {%4,%5,%6,%7}, {%8,%9}, {%0,%1,%2,%3};"
        : "+f"(c[0]), "+f"(c[1]), "+f"(c[2]), "+f"(c[3])
        : "r"(a[0]), "r"(a[1]), "r"(a[2]), "r"(a[3]), "r"(b[0]), "r"(b[1]));
}

// =============================================================== CSR build
__global__ void hist_kernel(const int* __restrict__ dst, int E) {
    int i = blockIdx.x * blockDim.x + threadIdx.x;
    if (i < E) atomicAdd(&g_deg[dst[i]], 1);
}

__global__ void scan_kernel(int E) {
    __shared__ int wsum[32];
    __shared__ int carry;
    if (threadIdx.x == 0) carry = 0;
    __syncthreads();
    int lane = threadIdx.x & 31, warp = threadIdx.x >> 5;
    for (int base = 0; base < NN; base += 1024) {
        int i = base + (int)threadIdx.x;
        int v = (i < NN) ? g_deg[i] : 0;
        int x = v;
        #pragma unroll
        for (int o = 1; o < 32; o <<= 1) {
            int y = __shfl_up_sync(0xffffffffu, x, o);
            if (lane >= o) x += y;
        }
        if (lane == 31) wsum[warp] = x;
        __syncthreads();
        if (warp == 0) {
            int t = wsum[lane];
            #pragma unroll
            for (int o = 1; o < 32; o <<= 1) {
                int y = __shfl_up_sync(0xffffffffu, t, o);
                if (lane >= o) t += y;
            }
            wsum[lane] = t;
        }
        __syncthreads();
        int incl = x + (warp > 0 ? wsum[warp - 1] : 0);
        int excl = carry + incl - v;
        if (i < NN) { g_off[i] = excl; g_cur[i] = excl; }
        __syncthreads();
        if (threadIdx.x == 1023) carry += incl;
        __syncthreads();
    }
    if (threadIdx.x == 0) g_off[NN] = E;
}

__global__ void scatter_kernel(const int* __restrict__ src,
                               const int* __restrict__ dst,
                               const float* __restrict__ val, int E) {
    int i = blockIdx.x * blockDim.x + threadIdx.x;
    if (i < E) {
        int p = atomicAdd(&g_cur[dst[i]], 1);
        g_esrc[p] = src[i];
        g_eval[p] = val[i];
    }
}

// =============================================================== split prep
__global__ void split_x_kernel(const float* __restrict__ x, int n4) {
    int i = blockIdx.x * blockDim.x + threadIdx.x;
    if (i >= n4) return;
    float4 v = ((const float4*)x)[i];
    union { __nv_bfloat16 b[4]; uint2 u; } H, L;
    H.b[0] = __float2bfloat16(v.x); L.b[0] = __float2bfloat16(v.x - __bfloat162float(H.b[0]));
    H.b[1] = __float2bfloat16(v.y); L.b[1] = __float2bfloat16(v.y - __bfloat162float(H.b[1]));
    H.b[2] = __float2bfloat16(v.z); L.b[2] = __float2bfloat16(v.z - __bfloat162float(H.b[2]));
    H.b[3] = __float2bfloat16(v.w); L.b[3] = __float2bfloat16(v.w - __bfloat162float(H.b[3]));
    ((uint2*)g_xhi)[i] = H.u;
    ((uint2*)g_xlo)[i] = L.u;
}

__global__ void zero_pad_kernel(int M) {
    int i = blockIdx.x * blockDim.x + threadIdx.x;
    size_t base = (size_t)M * CH;
    size_t total = (size_t)PAD_M * CH;
    size_t idx = base + i;
    if (idx < total) {
        g_xhi[idx] = __float2bfloat16(0.f);
        g_xlo[idx] = __float2bfloat16(0.f);
    }
}

__global__ void split_wt_kernel(const float* __restrict__ W) {
    int k = threadIdx.x;
    int n = blockIdx.x;
    float w = W[k * CH + n];
    __nv_bfloat16 h = __float2bfloat16(w);
    g_wthi[n * CH + k] = h;
    g_wtlo[n * CH + k] = __float2bfloat16(w - __bfloat162float(h));
}

// =============================================================== mma.sync GEMM
// g_xwh[M, bn..bn+127] = x @ W[:, bn..bn+127] via split-bf16
// (D += AhiBhi + AhiBlo + AloBhi, fp32 accum, fp16 output).
#define SWZ(r, c) ((uint32_t)((r) * 64 + (((c) ^ ((r) & 3)) * 16)))
#define GEMM_SMEM 65536

__global__ __launch_bounds__(256, 2) void gemm_mma(int M, int bn) {
    extern __shared__ char smem[];
    const uint32_t sb = smem_u32(smem);
    const int tid  = threadIdx.x;
    const int lane = tid & 31;
    const int wid  = tid >> 5;
    const int warp_m = (wid & 3) * 32;   // 0,32,64,96
    const int warp_n = (wid >> 2) * 64;  // 0,64
    const size_t arow = (size_t)blockIdx.x * 128;

    float acc[2][8][4];
    #pragma unroll
    for (int mt = 0; mt < 2; mt++)
        #pragma unroll
        for (int nt = 0; nt < 8; nt++)
            #pragma unroll
            for (int j = 0; j < 4; j++) acc[mt][nt][j] = 0.f;

    auto fill = [&](int buf, int ch) {
        const int k0 = ch * 32;
        const uint32_t base = sb + buf * 32768;
        #pragma unroll
        for (int i = 0; i < 2; i++) {
            int chunk = tid + i * 256;         // 0..511
            int r = chunk >> 2, c = chunk & 3; // row 0..127, 16B-chunk 0..3
            uint32_t so = SWZ(r, c);
            size_t ga = (arow + r) * CH + k0 + c * 8;
            size_t gb = (size_t)(bn + r) * CH + k0 + c * 8;
            cp_async16(base +     0 + so, &g_xhi[ga]);
            cp_async16(base +  8192 + so, &g_xlo[ga]);
            cp_async16(base + 16384 + so, &g_wthi[gb]);
            cp_async16(base + 24576 + so, &g_wtlo[gb]);
        }
    };

    auto compute = [&](int buf) {
        const uint32_t base = sb + buf * 32768;
        #pragma unroll
        for (int ks = 0; ks < 2; ks++) {
            uint32_t a_hi[2][4], a_lo[2][4];
            const int achunk = 2 * ks + (lane >> 4);
            #pragma unroll
            for (int mt = 0; mt < 2; mt++) {
                int r = warp_m + mt * 16 + (lane & 15);
                uint32_t ad = base + SWZ(r, achunk);
                ldsm_x4(a_hi[mt], ad);
                ldsm_x4(a_lo[mt], ad + 8192);
            }
            #pragma unroll
            for (int np = 0; np < 4; np++) {
                int nr = warp_n + np * 16 + (lane & 7) + ((lane & 16) ? 8 : 0);
                int bchunk = 2 * ks + ((lane >> 3) & 1);
                uint32_t bd = base + 16384 + SWZ(nr, bchunk);
                uint32_t bhi[4], blo[4];
                ldsm_x4(bhi, bd);
                ldsm_x4(blo, bd + 8192);
                #pragma unroll
                for (int h = 0; h < 2; h++) {
                    int nt = np * 2 + h;
                    #pragma unroll
                    for (int mt = 0; mt < 2; mt++) {
                        mma_bf16(acc[mt][nt], a_hi[mt], &bhi[2 * h]);
                        mma_bf16(acc[mt][nt], a_hi[mt], &blo[2 * h]);
                        mma_bf16(acc[mt][nt], a_lo[mt], &bhi[2 * h]);
                    }
                }
            }
        }
    };

    fill(0, 0);
    cp_commit();
    #pragma unroll 1
    for (int ch = 0; ch < 8; ch++) {
        if (ch < 7) {
            fill((ch + 1) & 1, ch + 1);
            cp_commit();
            cp_wait<1>();
        } else {
            cp_wait<0>();
        }
        __syncthreads();
        compute(ch & 1);
        __syncthreads();
    }

    // epilogue: fp32 acc -> fp16 xw
    #pragma unroll
    for (int mt = 0; mt < 2; mt++) {
        size_t r0 = arow + warp_m + mt * 16 + (lane >> 2);
        #pragma unroll
        for (int nt = 0; nt < 8; nt++) {
            int gc = bn + warp_n + nt * 8 + 2 * (lane & 3);
            if (r0 < (size_t)M)
                *(__half2*)&g_xwh[r0 * CH + gc] =
                    __floats2half2_rn(acc[mt][nt][0], acc[mt][nt][1]);
            if (r0 + 8 < (size_t)M)
                *(__half2*)&g_xwh[(r0 + 8) * CH + gc] =
                    __floats2half2_rn(acc[mt][nt][2], acc[mt][nt][3]);
        }
    }
}

// =============================================================== gather
// out[d][c0+c..] = b[..] + sum_{edges to d} val * xwh[src][..]  (fp16 reads,
// fp32 accum). One 128-channel half per launch; 16 threads x 8ch per node,
// 16 nodes per 256-thread block. Per edge access = 256B contiguous.
__global__ __launch_bounds__(256) void gather_half(const float* __restrict__ bias,
                                                   float* __restrict__ out, int c0) {
    int node = blockIdx.x * 16 + (threadIdx.x >> 4);
    if (node >= NN) return;
    int c = c0 + ((threadIdx.x & 15) << 3);   // 8 halves per thread
    int s = g_off[node], e = g_off[node + 1];

    float acc[8];
    #pragma unroll
    for (int j = 0; j < 8; j++) acc[j] = bias[c + j];

    auto fma8 = [&](float v, uint4 u) {
        const __half2* h = (const __half2*)&u;
        #pragma unroll
        for (int q = 0; q < 4; q++) {
            float2 f = __half22float2(h[q]);
            acc[2 * q]     += v * f.x;
            acc[2 * q + 1] += v * f.y;
        }
    };

    int j = s;
    for (; j + 4 <= e; j += 4) {
        int   s0 = g_esrc[j],     s1 = g_esrc[j + 1];
        int   s2 = g_esrc[j + 2], s3 = g_esrc[j + 3];
        float v0 = g_eval[j],     v1 = g_eval[j + 1];
        float v2 = g_eval[j + 2], v3 = g_eval[j + 3];
        uint4 x0 = *(const uint4*)&g_xwh[(size_t)s0 * CH + c];
        uint4 x1 = *(const uint4*)&g_xwh[(size_t)s1 * CH + c];
        uint4 x2 = *(const uint4*)&g_xwh[(size_t)s2 * CH + c];
        uint4 x3 = *(const uint4*)&g_xwh[(size_t)s3 * CH + c];
        fma8(v0, x0);
        fma8(v1, x1);
        fma8(v2, x2);
        fma8(v3, x3);
    }
    for (; j < e; ++j) {
        float v = g_eval[j];
        uint4 x0 = *(const uint4*)&g_xwh[(size_t)g_esrc[j] * CH + c];
        fma8(v, x0);
    }

    float4 o0 = make_float4(acc[0], acc[1], acc[2], acc[3]);
    float4 o1 = make_float4(acc[4], acc[5], acc[6], acc[7]);
    *(float4*)&out[(size_t)node * CH + c]     = o0;
    *(float4*)&out[(size_t)node * CH + c + 4] = o1;
}

// =============================================================== launch
// DAG (identical to the measured-best R7 structure):
//   main:  split_x -> pad -> split_wt -> gemm(n=0..127) -> gemm(n=128..255)
//   sB:    memset(deg) -> hist -> scan -> scatter
//   sC:    [gemm0 && scatter] -> gather cols 0..127
//   main:  [gemm1 && scatter] -> gather cols 128..255 -> join sC
extern "C" void kernel_launch(void* const* d_in, const int* in_sizes, int n_in,
                              void* d_out, int out_size) {
    const float* x    = (const float*)d_in[0];   // [N, 256]
    const float* W    = (const float*)d_in[1];   // [256, 256]
    const float* bias = (const float*)d_in[2];   // [256]
    const int*   esrc = (const int*)d_in[3];     // [E]
    const int*   edst = (const int*)d_in[4];     // [E]
    const float* eval = (const float*)d_in[5];   // [E]
    float* out = (float*)d_out;

    int M = in_sizes[0] / CH;   // 50000
    int E = in_sizes[3];        // 800000

    cudaFuncSetAttribute(gemm_mma, cudaFuncAttributeMaxDynamicSharedMemorySize,
                         GEMM_SMEM);

    cudaStream_t sB, sC;
    cudaStreamCreateWithFlags(&sB, cudaStreamNonBlocking);
    cudaStreamCreateWithFlags(&sC, cudaStreamNonBlocking);
    cudaEvent_t evRoot, evS, evG0, evC;
    cudaEventCreateWithFlags(&evRoot, cudaEventDisableTiming);
    cudaEventCreateWithFlags(&evS,    cudaEventDisableTiming);
    cudaEventCreateWithFlags(&evG0,   cudaEventDisableTiming);
    cudaEventCreateWithFlags(&evC,    cudaEventDisableTiming);

    // fork sB off the (captured) default stream
    cudaEventRecord(evRoot, 0);
    cudaStreamWaitEvent(sB, evRoot, 0);

    // ---- branch B: CSR-by-dst build ----
    void* degp = nullptr;
    cudaGetSymbolAddress(&degp, g_deg);
    cudaMemsetAsync(degp, 0, NN * sizeof(int), sB);
    hist_kernel<<<(E + 255) / 256, 256, 0, sB>>>(edst, E);
    scan_kernel<<<1, 1024, 0, sB>>>(E);
    scatter_kernel<<<(E + 255) / 256, 256, 0, sB>>>(esrc, edst, eval, E);
    cudaEventRecord(evS, sB);

    // ---- main branch: split prep + GEMM halves ----
    int n4 = (M * CH) / 4;
    split_x_kernel<<<(n4 + 255) / 256, 256>>>(x, n4);
    int padn = (PAD_M - M) * CH;
    if (padn > 0) zero_pad_kernel<<<(padn + 255) / 256, 256>>>(M);
    split_wt_kernel<<<CH, CH>>>(W);
    int mblk = (M + 127) / 128;   // 391
    gemm_mma<<<mblk, 256, GEMM_SMEM>>>(M, 0);
    cudaEventRecord(evG0, 0);
    gemm_mma<<<mblk, 256, GEMM_SMEM>>>(M, 128);

    // ---- branch C: gather cols 0..127 (overlaps gemm half 1) ----
    cudaStreamWaitEvent(sC, evG0, 0);
    cudaStreamWaitEvent(sC, evS, 0);
    gather_half<<<(NN + 15) / 16, 256, 0, sC>>>(bias, out, 0);
    cudaEventRecord(evC, sC);

    // ---- main branch: gather cols 128..255, then join everything ----
    cudaStreamWaitEvent(0, evS, 0);
    gather_half<<<(NN + 15) / 16, 256>>>(bias, out, 128);
    cudaStreamWaitEvent(0, evC, 0);

    cudaEventDestroy(evRoot);
    cudaEventDestroy(evS);
    cudaEventDestroy(evG0);
    cudaEventDestroy(evC);
    cudaStreamDestroy(sB);
    cudaStreamDestroy(sC);
}

// round 11
// speedup vs baseline: 1.0859x; 1.0428x over previous
#include <cuda_runtime.h>
#include <cuda_bf16.h>
#include <cuda_fp16.h>
#include <cstdint>

#define NN 50000
#define EE 800000
#define CH 256
#define PAD_M 50048          // 391 * 128

// ---- scratch (device globals; no allocation allowed) ----
__device__ __align__(16) __half g_xwh[(size_t)NN * CH];            // x @ W (25.6 MB, fp16)
__device__ int   g_deg[NN];
__device__ int   g_off[NN + 1];
__device__ int   g_cur[NN];
__device__ __align__(16) int2 g_epack[EE];                         // (src, val)
__device__ __align__(16) __nv_bfloat16 g_xhi[(size_t)PAD_M * CH];  // 25.6 MB
__device__ __align__(16) __nv_bfloat16 g_xlo[(size_t)PAD_M * CH];  // 25.6 MB
__device__ __align__(16) __nv_bfloat16 g_wthi[CH * CH];            // W^T hi [n][k]
__device__ __align__(16) __nv_bfloat16 g_wtlo[CH * CH];            // W^T lo [n][k]

// =============================================================== helpers
__device__ __forceinline__ uint32_t smem_u32(const void* p) {
    uint32_t a;
    asm("{ .reg .u64 t; cvta.to.shared.u64 t, %1; cvt.u32.u64 %0, t; }"
        : "=r"(a) : "l"(p));
    return a;
}

__device__ __forceinline__ void cp_async16(uint32_t s, const void* g) {
    asm volatile("cp.async.cg.shared.global [%0], [%1], 16;" :: "r"(s), "l"(g));
}
__device__ __forceinline__ void cp_commit() {
    asm volatile("cp.async.commit_group;" ::: "memory");
}
template <int N>
__device__ __forceinline__ void cp_wait() {
    asm volatile("cp.async.wait_group %0;" :: "n"(N) : "memory");
}

__device__ __forceinline__ void ldsm_x4(uint32_t* r, uint32_t addr) {
    asm volatile("ldmatrix.sync.aligned.m8n8.x4.shared.b16 {%0,%1,%2,%3}, [%4];"
                 : "=r"(r[0]), "=r"(r[1]), "=r"(r[2]), "=r"(r[3]) : "r"(addr));
}

// D(fp32) += A(bf16) * B(bf16), m16n8k16, A row-major frag, B col-major frag
__device__ __forceinline__ void mma_bf16(float* c, const uint32_t* a, const uint32_t* b) {
    asm volatile(
        "mma.sync.aligned.m16n8k16.row.col.f32.bf16.bf16.f32 "
        "{%0,%1,%2,%3}, {%4,%5,%6,%7}, {%8,%9}, {%0,%1,%2,%3};"
        : "+f"(c[0]), "+f"(c[1]), "+f"(c[2]), "+f"(c[3])
        : "r"(a[0]), "r"(a[1]), "r"(a[2]), "r"(a[3]), "r"(b[0]), "r"(b[1]));
}

// =============================================================== CSR build
__global__ void hist_kernel(const int* __restrict__ dst, int E) {
    int i = blockIdx.x * blockDim.x + threadIdx.x;
    if (i < E) atomicAdd(&g_deg[dst[i]], 1);
}

__global__ void scan_kernel(int E) {
    __shared__ int wsum[32];
    __shared__ int carry;
    if (threadIdx.x == 0) carry = 0;
    __syncthreads();
    int lane = threadIdx.x & 31, warp = threadIdx.x >> 5;
    for (int base = 0; base < NN; base += 1024) {
        int i = base + (int)threadIdx.x;
        int v = (i < NN) ? g_deg[i] : 0;
        int x = v;
        #pragma unroll
        for (int o = 1; o < 32; o <<= 1) {
            int y = __shfl_up_sync(0xffffffffu, x, o);
            if (lane >= o) x += y;
        }
        if (lane == 31) wsum[warp] = x;
        __syncthreads();
        if (warp == 0) {
            int t = wsum[lane];
            #pragma unroll
            for (int o = 1; o < 32; o <<= 1) {
                int y = __shfl_up_sync(0xffffffffu, t, o);
                if (lane >= o) t += y;
            }
            wsum[lane] = t;
        }
        __syncthreads();
        int incl = x + (warp > 0 ? wsum[warp - 1] : 0);
        int excl = carry + incl - v;
        if (i < NN) { g_off[i] = excl; g_cur[i] = excl; }
        __syncthreads();
        if (threadIdx.x == 1023) carry += incl;
        __syncthreads();
    }
    if (threadIdx.x == 0) g_off[NN] = E;
}

__global__ void scatter_kernel(const int* __restrict__ src,
                               const int* __restrict__ dst,
                               const float* __restrict__ val, int E) {
    int i = blockIdx.x * blockDim.x + threadIdx.x;
    if (i < E) {
        int p = atomicAdd(&g_cur[dst[i]], 1);
        g_epack[p] = make_int2(src[i], __float_as_int(val[i]));
    }
}

// =============================================================== split prep
__global__ void split_x_kernel(const float* __restrict__ x, int n4) {
    int i = blockIdx.x * blockDim.x + threadIdx.x;
    if (i >= n4) return;
    float4 v = ((const float4*)x)[i];
    union { __nv_bfloat16 b[4]; uint2 u; } H, L;
    H.b[0] = __float2bfloat16(v.x); L.b[0] = __float2bfloat16(v.x - __bfloat162float(H.b[0]));
    H.b[1] = __float2bfloat16(v.y); L.b[1] = __float2bfloat16(v.y - __bfloat162float(H.b[1]));
    H.b[2] = __float2bfloat16(v.z); L.b[2] = __float2bfloat16(v.z - __bfloat162float(H.b[2]));
    H.b[3] = __float2bfloat16(v.w); L.b[3] = __float2bfloat16(v.w - __bfloat162float(H.b[3]));
    ((uint2*)g_xhi)[i] = H.u;
    ((uint2*)g_xlo)[i] = L.u;
}

__global__ void zero_pad_kernel(int M) {
    int i = blockIdx.x * blockDim.x + threadIdx.x;
    size_t base = (size_t)M * CH;
    size_t total = (size_t)PAD_M * CH;
    size_t idx = base + i;
    if (idx < total) {
        g_xhi[idx] = __float2bfloat16(0.f);
        g_xlo[idx] = __float2bfloat16(0.f);
    }
}

__global__ void split_wt_kernel(const float* __restrict__ W) {
    int k = threadIdx.x;
    int n = blockIdx.x;
    float w = W[k * CH + n];
    __nv_bfloat16 h = __float2bfloat16(w);
    g_wthi[n * CH + k] = h;
    g_wtlo[n * CH + k] = __float2bfloat16(w - __bfloat162float(h));
}

// =============================================================== mma.sync GEMM
// g_xwh[M, bn..bn+127] = x @ W[:, bn..bn+127] via split-bf16
// (D += AhiBhi + AhiBlo + AloBhi, fp32 accum, fp16 output).
#define SWZ(r, c) ((uint32_t)((r) * 64 + (((c) ^ ((r) & 3)) * 16)))
#define GEMM_SMEM 65536

__global__ __launch_bounds__(256, 2) void gemm_mma(int M, int bn) {
    extern __shared__ char smem[];
    const uint32_t sb = smem_u32(smem);
    const int tid  = threadIdx.x;
    const int lane = tid & 31;
    const int wid  = tid >> 5;
    const int warp_m = (wid & 3) * 32;   // 0,32,64,96
    const int warp_n = (wid >> 2) * 64;  // 0,64
    const size_t arow = (size_t)blockIdx.x * 128;

    float acc[2][8][4];
    #pragma unroll
    for (int mt = 0; mt < 2; mt++)
        #pragma unroll
        for (int nt = 0; nt < 8; nt++)
            #pragma unroll
            for (int j = 0; j < 4; j++) acc[mt][nt][j] = 0.f;

    auto fill = [&](int buf, int ch) {
        const int k0 = ch * 32;
        const uint32_t base = sb + buf * 32768;
        #pragma unroll
        for (int i = 0; i < 2; i++) {
            int chunk = tid + i * 256;         // 0..511
            int r = chunk >> 2, c = chunk & 3; // row 0..127, 16B-chunk 0..3
            uint32_t so = SWZ(r, c);
            size_t ga = (arow + r) * CH + k0 + c * 8;
            size_t gb = (size_t)(bn + r) * CH + k0 + c * 8;
            cp_async16(base +     0 + so, &g_xhi[ga]);
            cp_async16(base +  8192 + so, &g_xlo[ga]);
            cp_async16(base + 16384 + so, &g_wthi[gb]);
            cp_async16(base + 24576 + so, &g_wtlo[gb]);
        }
    };

    auto compute = [&](int buf) {
        const uint32_t base = sb + buf * 32768;
        #pragma unroll
        for (int ks = 0; ks < 2; ks++) {
            uint32_t a_hi[2][4], a_lo[2][4];
            const int achunk = 2 * ks + (lane >> 4);
            #pragma unroll
            for (int mt = 0; mt < 2; mt++) {
                int r = warp_m + mt * 16 + (lane & 15);
                uint32_t ad = base + SWZ(r, achunk);
                ldsm_x4(a_hi[mt], ad);
                ldsm_x4(a_lo[mt], ad + 8192);
            }
            #pragma unroll
            for (int np = 0; np < 4; np++) {
                int nr = warp_n + np * 16 + (lane & 7) + ((lane & 16) ? 8 : 0);
                int bchunk = 2 * ks + ((lane >> 3) & 1);
                uint32_t bd = base + 16384 + SWZ(nr, bchunk);
                uint32_t bhi[4], blo[4];
                ldsm_x4(bhi, bd);
                ldsm_x4(blo, bd + 8192);
                #pragma unroll
                for (int h = 0; h < 2; h++) {
                    int nt = np * 2 + h;
                    #pragma unroll
                    for (int mt = 0; mt < 2; mt++) {
                        mma_bf16(acc[mt][nt], a_hi[mt], &bhi[2 * h]);
                        mma_bf16(acc[mt][nt], a_hi[mt], &blo[2 * h]);
                        mma_bf16(acc[mt][nt], a_lo[mt], &bhi[2 * h]);
                    }
                }
            }
        }
    };

    fill(0, 0);
    cp_commit();
    #pragma unroll 1
    for (int ch = 0; ch < 8; ch++) {
        if (ch < 7) {
            fill((ch + 1) & 1, ch + 1);
            cp_commit();
            cp_wait<1>();
        } else {
            cp_wait<0>();
        }
        __syncthreads();
        compute(ch & 1);
        __syncthreads();
    }

    // epilogue: fp32 acc -> fp16 xw
    #pragma unroll
    for (int mt = 0; mt < 2; mt++) {
        size_t r0 = arow + warp_m + mt * 16 + (lane >> 2);
        #pragma unroll
        for (int nt = 0; nt < 8; nt++) {
            int gc = bn + warp_n + nt * 8 + 2 * (lane & 3);
            if (r0 < (size_t)M)
                *(__half2*)&g_xwh[r0 * CH + gc] =
                    __floats2half2_rn(acc[mt][nt][0], acc[mt][nt][1]);
            if (r0 + 8 < (size_t)M)
                *(__half2*)&g_xwh[(r0 + 8) * CH + gc] =
                    __floats2half2_rn(acc[mt][nt][2], acc[mt][nt][3]);
        }
    }
}

// =============================================================== gather
// out[d][c0+c..] = b[..] + sum_{edges to d} val * xwh[src][..]  (fp16 reads,
// fp32 accum). One 128-channel half per launch; 16 threads x 8ch per node,
// 16 nodes per 256-thread block. Batch-8 inner loop: 8 independent meta
// loads, then 8 independent row loads -> 2 exposed latencies per 8 edges
// (was per 4), doubling per-thread MLP.
__global__ __launch_bounds__(256) void gather_half(const float* __restrict__ bias,
                                                   float* __restrict__ out, int c0) {
    int node = blockIdx.x * 16 + (threadIdx.x >> 4);
    if (node >= NN) return;
    int c = c0 + ((threadIdx.x & 15) << 3);   // 8 halves per thread
    int s = g_off[node], e = g_off[node + 1];

    float acc[8];
    #pragma unroll
    for (int j = 0; j < 8; j++) acc[j] = bias[c + j];

    auto fma8 = [&](float v, uint4 u) {
        const __half2* h = (const __half2*)&u;
        #pragma unroll
        for (int q = 0; q < 4; q++) {
            float2 f = __half22float2(h[q]);
            acc[2 * q]     += v * f.x;
            acc[2 * q + 1] += v * f.y;
        }
    };

    const __half* __restrict__ xw = g_xwh;
    int j = s;
    for (; j + 8 <= e; j += 8) {
        int2 m[8];
        #pragma unroll
        for (int q = 0; q < 8; q++) m[q] = __ldg(&g_epack[j + q]);
        uint4 xv[8];
        #pragma unroll
        for (int q = 0; q < 8; q++)
            xv[q] = __ldg((const uint4*)&xw[(size_t)m[q].x * CH + c]);
        #pragma unroll
        for (int q = 0; q < 8; q++) fma8(__int_as_float(m[q].y), xv[q]);
    }
    if (j + 4 <= e) {
        int2 m[4];
        #pragma unroll
        for (int q = 0; q < 4; q++) m[q] = __ldg(&g_epack[j + q]);
        uint4 xv[4];
        #pragma unroll
        for (int q = 0; q < 4; q++)
            xv[q] = __ldg((const uint4*)&xw[(size_t)m[q].x * CH + c]);
        #pragma unroll
        for (int q = 0; q < 4; q++) fma8(__int_as_float(m[q].y), xv[q]);
        j += 4;
    }
    for (; j < e; ++j) {
        int2 m = __ldg(&g_epack[j]);
        uint4 xv = __ldg((const uint4*)&xw[(size_t)m.x * CH + c]);
        fma8(__int_as_float(m.y), xv);
    }

    float4 o0 = make_float4(acc[0], acc[1], acc[2], acc[3]);
    float4 o1 = make_float4(acc[4], acc[5], acc[6], acc[7]);
    *(float4*)&out[(size_t)node * CH + c]     = o0;
    *(float4*)&out[(size_t)node * CH + c + 4] = o1;
}

// =============================================================== launch
// DAG (identical to the measured-best R10 structure):
//   main:  split_x -> pad -> split_wt -> gemm(n=0..127) -> gemm(n=128..255)
//   sB:    memset(deg) -> hist -> scan -> scatter
//   sC:    [gemm0 && scatter] -> gather cols 0..127
//   main:  [gemm1 && scatter] -> gather cols 128..255 -> join sC
extern "C" void kernel_launch(void* const* d_in, const int* in_sizes, int n_in,
                              void* d_out, int out_size) {
    const float* x    = (const float*)d_in[0];   // [N, 256]
    const float* W    = (const float*)d_in[1];   // [256, 256]
    const float* bias = (const float*)d_in[2];   // [256]
    const int*   esrc = (const int*)d_in[3];     // [E]
    const int*   edst = (const int*)d_in[4];     // [E]
    const float* eval = (const float*)d_in[5];   // [E]
    float* out = (float*)d_out;

    int M = in_sizes[0] / CH;   // 50000
    int E = in_sizes[3];        // 800000

    cudaFuncSetAttribute(gemm_mma, cudaFuncAttributeMaxDynamicSharedMemorySize,
                         GEMM_SMEM);

    cudaStream_t sB, sC;
    cudaStreamCreateWithFlags(&sB, cudaStreamNonBlocking);
    cudaStreamCreateWithFlags(&sC, cudaStreamNonBlocking);
    cudaEvent_t evRoot, evS, evG0, evC;
    cudaEventCreateWithFlags(&evRoot, cudaEventDisableTiming);
    cudaEventCreateWithFlags(&evS,    cudaEventDisableTiming);
    cudaEventCreateWithFlags(&evG0,   cudaEventDisableTiming);
    cudaEventCreateWithFlags(&evC,    cudaEventDisableTiming);

    // fork sB off the (captured) default stream
    cudaEventRecord(evRoot, 0);
    cudaStreamWaitEvent(sB, evRoot, 0);

    // ---- branch B: CSR-by-dst build ----
    void* degp = nullptr;
    cudaGetSymbolAddress(&degp, g_deg);
    cudaMemsetAsync(degp, 0, NN * sizeof(int), sB);
    hist_kernel<<<(E + 255) / 256, 256, 0, sB>>>(edst, E);
    scan_kernel<<<1, 1024, 0, sB>>>(E);
    scatter_kernel<<<(E + 255) / 256, 256, 0, sB>>>(esrc, edst, eval, E);
    cudaEventRecord(evS, sB);

    // ---- main branch: split prep + GEMM halves ----
    int n4 = (M * CH) / 4;
    split_x_kernel<<<(n4 + 255) / 256, 256>>>(x, n4);
    int padn = (PAD_M - M) * CH;
    if (padn > 0) zero_pad_kernel<<<(padn + 255) / 256, 256>>>(M);
    split_wt_kernel<<<CH, CH>>>(W);
    int mblk = (M + 127) / 128;   // 391
    gemm_mma<<<mblk, 256, GEMM_SMEM>>>(M, 0);
    cudaEventRecord(evG0, 0);
    gemm_mma<<<mblk, 256, GEMM_SMEM>>>(M, 128);

    // ---- branch C: gather cols 0..127 (overlaps gemm half 1) ----
    cudaStreamWaitEvent(sC, evG0, 0);
    cudaStreamWaitEvent(sC, evS, 0);
    gather_half<<<(NN + 15) / 16, 256, 0, sC>>>(bias, out, 0);
    cudaEventRecord(evC, sC);

    // ---- main branch: gather cols 128..255, then join everything ----
    cudaStreamWaitEvent(0, evS, 0);
    gather_half<<<(NN + 15) / 16, 256>>>(bias, out, 128);
    cudaStreamWaitEvent(0, evC, 0);

    cudaEventDestroy(evRoot);
    cudaEventDestroy(evS);
    cudaEventDestroy(evG0);
    cudaEventDestroy(evC);
    cudaStreamDestroy(sB);
    cudaStreamDestroy(sC);
}

// round 12
// speedup vs baseline: 1.0991x; 1.0122x over previous
#include <cuda_runtime.h>
#include <cuda_bf16.h>
#include <cuda_fp16.h>
#include <cstdint>

#define NN 50000
#define EE 800000
#define CH 256
#define PAD_M 50048          // 391 * 128

// ---- scratch (device globals; no allocation allowed) ----
__device__ __align__(16) __half g_xwh[(size_t)NN * CH];            // x @ W (25.6 MB, fp16)
__device__ int   g_deg[NN];
__device__ int   g_off[NN + 1];
__device__ int   g_cur[NN];
__device__ __align__(16) int2 g_epack[EE];                         // (src, val)
__device__ __align__(16) __nv_bfloat16 g_xhi[(size_t)PAD_M * CH];  // 25.6 MB
__device__ __align__(16) __nv_bfloat16 g_xlo[(size_t)PAD_M * CH];  // 25.6 MB
__device__ __align__(16) __nv_bfloat16 g_wthi[CH * CH];            // W^T hi [n][k]
__device__ __align__(16) __nv_bfloat16 g_wtlo[CH * CH];            // W^T lo [n][k]

// =============================================================== helpers
__device__ __forceinline__ uint32_t smem_u32(const void* p) {
    uint32_t a;
    asm("{ .reg .u64 t; cvta.to.shared.u64 t, %1; cvt.u32.u64 %0, t; }"
        : "=r"(a) : "l"(p));
    return a;
}

__device__ __forceinline__ void cp_async16(uint32_t s, const void* g) {
    asm volatile("cp.async.cg.shared.global [%0], [%1], 16;" :: "r"(s), "l"(g));
}
__device__ __forceinline__ void cp_commit() {
    asm volatile("cp.async.commit_group;" ::: "memory");
}
template <int N>
__device__ __forceinline__ void cp_wait() {
    asm volatile("cp.async.wait_group %0;" :: "n"(N) : "memory");
}

__device__ __forceinline__ void ldsm_x4(uint32_t* r, uint32_t addr) {
    asm volatile("ldmatrix.sync.aligned.m8n8.x4.shared.b16 {%0,%1,%2,%3}, [%4];"
                 : "=r"(r[0]), "=r"(r[1]), "=r"(r[2]), "=r"(r[3]) : "r"(addr));
}

// D(fp32) += A(bf16) * B(bf16), m16n8k16, A row-major frag, B col-major frag
__device__ __forceinline__ void mma_bf16(float* c, const uint32_t* a, const uint32_t* b) {
    asm volatile(
        "mma.sync.aligned.m16n8k16.row.col.f32.bf16.bf16.f32 "
        "{%0,%1,%2,%3}, {%4,%5,%6,%7}, {%8,%9}, {%0,%1,%2,%3};"
        : "+f"(c[0]), "+f"(c[1]), "+f"(c[2]), "+f"(c[3])
        : "r"(a[0]), "r"(a[1]), "r"(a[2]), "r"(a[3]), "r"(b[0]), "r"(b[1]));
}

// =============================================================== CSR build
__global__ void hist_kernel(const int* __restrict__ dst, int E) {
    int i = blockIdx.x * blockDim.x + threadIdx.x;
    if (i < E) atomicAdd(&g_deg[dst[i]], 1);
}

__global__ void scan_kernel(int E) {
    __shared__ int wsum[32];
    __shared__ int carry;
    if (threadIdx.x == 0) carry = 0;
    __syncthreads();
    int lane = threadIdx.x & 31, warp = threadIdx.x >> 5;
    for (int base = 0; base < NN; base += 1024) {
        int i = base + (int)threadIdx.x;
        int v = (i < NN) ? g_deg[i] : 0;
        int x = v;
        #pragma unroll
        for (int o = 1; o < 32; o <<= 1) {
            int y = __shfl_up_sync(0xffffffffu, x, o);
            if (lane >= o) x += y;
        }
        if (lane == 31) wsum[warp] = x;
        __syncthreads();
        if (warp == 0) {
            int t = wsum[lane];
            #pragma unroll
            for (int o = 1; o < 32; o <<= 1) {
                int y = __shfl_up_sync(0xffffffffu, t, o);
                if (lane >= o) t += y;
            }
            wsum[lane] = t;
        }
        __syncthreads();
        int incl = x + (warp > 0 ? wsum[warp - 1] : 0);
        int excl = carry + incl - v;
        if (i < NN) { g_off[i] = excl; g_cur[i] = excl; }
        __syncthreads();
        if (threadIdx.x == 1023) carry += incl;
        __syncthreads();
    }
    if (threadIdx.x == 0) g_off[NN] = E;
}

__global__ void scatter_kernel(const int* __restrict__ src,
                               const int* __restrict__ dst,
                               const float* __restrict__ val, int E) {
    int i = blockIdx.x * blockDim.x + threadIdx.x;
    if (i < E) {
        int p = atomicAdd(&g_cur[dst[i]], 1);
        g_epack[p] = make_int2(src[i], __float_as_int(val[i]));
    }
}

// =============================================================== fused prep
// One launch: [0, n4)            -> split x (float4 units)
//             [n4, n4+npad)      -> zero pad rows (uint2 = 4 bf16 units)
//             [n4+npad, +65536)  -> W^T split (one element each)
__global__ void prep_kernel(const float* __restrict__ x,
                            const float* __restrict__ W,
                            int n4, int npad) {
    int i = blockIdx.x * blockDim.x + threadIdx.x;
    if (i < n4) {
        float4 v = ((const float4*)x)[i];
        union { __nv_bfloat16 b[4]; uint2 u; } H, L;
        H.b[0] = __float2bfloat16(v.x); L.b[0] = __float2bfloat16(v.x - __bfloat162float(H.b[0]));
        H.b[1] = __float2bfloat16(v.y); L.b[1] = __float2bfloat16(v.y - __bfloat162float(H.b[1]));
        H.b[2] = __float2bfloat16(v.z); L.b[2] = __float2bfloat16(v.z - __bfloat162float(H.b[2]));
        H.b[3] = __float2bfloat16(v.w); L.b[3] = __float2bfloat16(v.w - __bfloat162float(H.b[3]));
        ((uint2*)g_xhi)[i] = H.u;
        ((uint2*)g_xlo)[i] = L.u;
    } else if (i < n4 + npad) {
        int p = i - n4;            // pad in 4-element units starting at n4
        ((uint2*)g_xhi)[n4 + p] = make_uint2(0u, 0u);
        ((uint2*)g_xlo)[n4 + p] = make_uint2(0u, 0u);
    } else if (i < n4 + npad + CH * CH) {
        int t = i - n4 - npad;
        int k = t & (CH - 1);
        int n = t >> 8;
        float w = W[k * CH + n];
        __nv_bfloat16 h = __float2bfloat16(w);
        g_wthi[n * CH + k] = h;
        g_wtlo[n * CH + k] = __float2bfloat16(w - __bfloat162float(h));
    }
}

// =============================================================== mma.sync GEMM
// g_xwh[M, bn..bn+127] = x @ W[:, bn..bn+127] via split-bf16
// (D += AhiBhi + AhiBlo + AloBhi, fp32 accum, fp16 output).
#define SWZ(r, c) ((uint32_t)((r) * 64 + (((c) ^ ((r) & 3)) * 16)))
#define GEMM_SMEM 65536

__global__ __launch_bounds__(256, 2) void gemm_mma(int M, int bn) {
    extern __shared__ char smem[];
    const uint32_t sb = smem_u32(smem);
    const int tid  = threadIdx.x;
    const int lane = tid & 31;
    const int wid  = tid >> 5;
    const int warp_m = (wid & 3) * 32;   // 0,32,64,96
    const int warp_n = (wid >> 2) * 64;  // 0,64
    const size_t arow = (size_t)blockIdx.x * 128;

    float acc[2][8][4];
    #pragma unroll
    for (int mt = 0; mt < 2; mt++)
        #pragma unroll
        for (int nt = 0; nt < 8; nt++)
            #pragma unroll
            for (int j = 0; j < 4; j++) acc[mt][nt][j] = 0.f;

    auto fill = [&](int buf, int ch) {
        const int k0 = ch * 32;
        const uint32_t base = sb + buf * 32768;
        #pragma unroll
        for (int i = 0; i < 2; i++) {
            int chunk = tid + i * 256;         // 0..511
            int r = chunk >> 2, c = chunk & 3; // row 0..127, 16B-chunk 0..3
            uint32_t so = SWZ(r, c);
            size_t ga = (arow + r) * CH + k0 + c * 8;
            size_t gb = (size_t)(bn + r) * CH + k0 + c * 8;
            cp_async16(base +     0 + so, &g_xhi[ga]);
            cp_async16(base +  8192 + so, &g_xlo[ga]);
            cp_async16(base + 16384 + so, &g_wthi[gb]);
            cp_async16(base + 24576 + so, &g_wtlo[gb]);
        }
    };

    auto compute = [&](int buf) {
        const uint32_t base = sb + buf * 32768;
        #pragma unroll
        for (int ks = 0; ks < 2; ks++) {
            uint32_t a_hi[2][4], a_lo[2][4];
            const int achunk = 2 * ks + (lane >> 4);
            #pragma unroll
            for (int mt = 0; mt < 2; mt++) {
                int r = warp_m + mt * 16 + (lane & 15);
                uint32_t ad = base + SWZ(r, achunk);
                ldsm_x4(a_hi[mt], ad);
                ldsm_x4(a_lo[mt], ad + 8192);
            }
            #pragma unroll
            for (int np = 0; np < 4; np++) {
                int nr = warp_n + np * 16 + (lane & 7) + ((lane & 16) ? 8 : 0);
                int bchunk = 2 * ks + ((lane >> 3) & 1);
                uint32_t bd = base + 16384 + SWZ(nr, bchunk);
                uint32_t bhi[4], blo[4];
                ldsm_x4(bhi, bd);
                ldsm_x4(blo, bd + 8192);
                #pragma unroll
                for (int h = 0; h < 2; h++) {
                    int nt = np * 2 + h;
                    #pragma unroll
                    for (int mt = 0; mt < 2; mt++) {
                        mma_bf16(acc[mt][nt], a_hi[mt], &bhi[2 * h]);
                        mma_bf16(acc[mt][nt], a_hi[mt], &blo[2 * h]);
                        mma_bf16(acc[mt][nt], a_lo[mt], &bhi[2 * h]);
                    }
                }
            }
        }
    };

    fill(0, 0);
    cp_commit();
    #pragma unroll 1
    for (int ch = 0; ch < 8; ch++) {
        if (ch < 7) {
            fill((ch + 1) & 1, ch + 1);
            cp_commit();
            cp_wait<1>();
        } else {
            cp_wait<0>();
        }
        __syncthreads();
        compute(ch & 1);
        __syncthreads();
    }

    // epilogue: fp32 acc -> fp16 xw
    #pragma unroll
    for (int mt = 0; mt < 2; mt++) {
        size_t r0 = arow + warp_m + mt * 16 + (lane >> 2);
        #pragma unroll
        for (int nt = 0; nt < 8; nt++) {
            int gc = bn + warp_n + nt * 8 + 2 * (lane & 3);
            if (r0 < (size_t)M)
                *(__half2*)&g_xwh[r0 * CH + gc] =
                    __floats2half2_rn(acc[mt][nt][0], acc[mt][nt][1]);
            if (r0 + 8 < (size_t)M)
                *(__half2*)&g_xwh[(r0 + 8) * CH + gc] =
                    __floats2half2_rn(acc[mt][nt][2], acc[mt][nt][3]);
        }
    }
}

// =============================================================== gather
// out[d][c0+c..] = b[..] + sum_{edges to d} val * xwh[src][..]  (fp16 reads,
// fp32 accum). One 128-channel half per launch; 16 threads x 8ch per node,
// 16 nodes per 256-thread block. Fully predicated batch-8: EVERY edge is
// processed at MLP=8 (tail batches clamp the index and zero the weight;
// duplicate loads of row e-1 are L1 hits).
__global__ __launch_bounds__(256) void gather_half(const float* __restrict__ bias,
                                                   float* __restrict__ out, int c0) {
    int node = blockIdx.x * 16 + (threadIdx.x >> 4);
    if (node >= NN) return;
    int c = c0 + ((threadIdx.x & 15) << 3);   // 8 halves per thread
    int s = g_off[node], e = g_off[node + 1];

    float acc[8];
    #pragma unroll
    for (int j = 0; j < 8; j++) acc[j] = bias[c + j];

    auto fma8 = [&](float v, uint4 u) {
        const __half2* h = (const __half2*)&u;
        #pragma unroll
        for (int q = 0; q < 4; q++) {
            float2 f = __half22float2(h[q]);
            acc[2 * q]     += v * f.x;
            acc[2 * q + 1] += v * f.y;
        }
    };

    const __half* __restrict__ xw = g_xwh;
    for (int j = s; j < e; j += 8) {
        int2 m[8];
        #pragma unroll
        for (int q = 0; q < 8; q++) {
            int idx = j + q;
            if (idx >= e) idx = e - 1;
            m[q] = __ldg(&g_epack[idx]);
        }
        uint4 xv[8];
        #pragma unroll
        for (int q = 0; q < 8; q++)
            xv[q] = __ldg((const uint4*)&xw[(size_t)m[q].x * CH + c]);
        #pragma unroll
        for (int q = 0; q < 8; q++) {
            float v = (j + q < e) ? __int_as_float(m[q].y) : 0.f;
            fma8(v, xv[q]);
        }
    }

    float4 o0 = make_float4(acc[0], acc[1], acc[2], acc[3]);
    float4 o1 = make_float4(acc[4], acc[5], acc[6], acc[7]);
    *(float4*)&out[(size_t)node * CH + c]     = o0;
    *(float4*)&out[(size_t)node * CH + c + 4] = o1;
}

// =============================================================== launch
// DAG (R11 structure; sC now HIGH PRIORITY so gather h0 actually gets SMs
// while gemm1 drains instead of queueing behind its backfill):
//   main:  prep(fused) -> gemm(n=0..127) -> gemm(n=128..255)
//   sB:    memset(deg) -> hist -> scan -> scatter
//   sC(hi):[gemm0 && scatter] -> gather cols 0..127
//   main:  [gemm1 && scatter] -> gather cols 128..255 -> join sC
extern "C" void kernel_launch(void* const* d_in, const int* in_sizes, int n_in,
                              void* d_out, int out_size) {
    const float* x    = (const float*)d_in[0];   // [N, 256]
    const float* W    = (const float*)d_in[1];   // [256, 256]
    const float* bias = (const float*)d_in[2];   // [256]
    const int*   esrc = (const int*)d_in[3];     // [E]
    const int*   edst = (const int*)d_in[4];     // [E]
    const float* eval = (const float*)d_in[5];   // [E]
    float* out = (float*)d_out;

    int M = in_sizes[0] / CH;   // 50000
    int E = in_sizes[3];        // 800000

    cudaFuncSetAttribute(gemm_mma, cudaFuncAttributeMaxDynamicSharedMemorySize,
                         GEMM_SMEM);

    int prLow = 0, prHigh = 0;
    cudaDeviceGetStreamPriorityRange(&prLow, &prHigh);

    cudaStream_t sB, sC;
    cudaStreamCreateWithFlags(&sB, cudaStreamNonBlocking);
    cudaStreamCreateWithPriority(&sC, cudaStreamNonBlocking, prHigh);
    cudaEvent_t evRoot, evS, evG0, evC;
    cudaEventCreateWithFlags(&evRoot, cudaEventDisableTiming);
    cudaEventCreateWithFlags(&evS,    cudaEventDisableTiming);
    cudaEventCreateWithFlags(&evG0,   cudaEventDisableTiming);
    cudaEventCreateWithFlags(&evC,    cudaEventDisableTiming);

    // fork sB off the (captured) default stream
    cudaEventRecord(evRoot, 0);
    cudaStreamWaitEvent(sB, evRoot, 0);

    // ---- branch B: CSR-by-dst build ----
    void* degp = nullptr;
    cudaGetSymbolAddress(&degp, g_deg);
    cudaMemsetAsync(degp, 0, NN * sizeof(int), sB);
    hist_kernel<<<(E + 255) / 256, 256, 0, sB>>>(edst, E);
    scan_kernel<<<1, 1024, 0, sB>>>(E);
    scatter_kernel<<<(E + 255) / 256, 256, 0, sB>>>(esrc, edst, eval, E);
    cudaEventRecord(evS, sB);

    // ---- main branch: fused prep + GEMM halves ----
    int n4 = (M * CH) / 4;
    int npad = ((PAD_M - M) * CH) / 4;
    int ptotal = n4 + npad + CH * CH;
    prep_kernel<<<(ptotal + 255) / 256, 256>>>(x, W, n4, npad);
    int mblk = (M + 127) / 128;   // 391
    gemm_mma<<<mblk, 256, GEMM_SMEM>>>(M, 0);
    cudaEventRecord(evG0, 0);
    gemm_mma<<<mblk, 256, GEMM_SMEM>>>(M, 128);

    // ---- branch C (high priority): gather cols 0..127, overlaps gemm1 ----
    cudaStreamWaitEvent(sC, evG0, 0);
    cudaStreamWaitEvent(sC, evS, 0);
    gather_half<<<(NN + 15) / 16, 256, 0, sC>>>(bias, out, 0);
    cudaEventRecord(evC, sC);

    // ---- main branch: gather cols 128..255, then join everything ----
    cudaStreamWaitEvent(0, evS, 0);
    gather_half<<<(NN + 15) / 16, 256>>>(bias, out, 128);
    cudaStreamWaitEvent(0, evC, 0);

    cudaEventDestroy(evRoot);
    cudaEventDestroy(evS);
    cudaEventDestroy(evG0);
    cudaEventDestroy(evC);
    cudaStreamDestroy(sB);
    cudaStreamDestroy(sC);
}